// round 7
// baseline (speedup 1.0000x reference)
#include <cuda_runtime.h>
#include <cuda_fp16.h>
#include <cstdint>

#define DIM 128
#define LOGN 13
#define THREADS 512
#define SCALE 0.17677669529663688f   // 32^-0.5

// ---- dynamic smem byte offsets ----
// Xh : 128 rows x 68 half2 (fp16 x tile, 272B row stride -> LDSM-friendly)
// M  : 2 buffers x 128 e-rows x 136 half (Mt[e][d], 272B stride)
//      (also reused as 128 x 132 f32 scratch for coalesced v stage-in/out)
// SS : ssA[4][64], scA[4][64] f32
// W0 : per-row own-weight, 128 f32
#define SMO_XH 0
#define SMO_M  34816
#define MBUF   34816
#define SMO_SS (SMO_M + 2 * MBUF)     // 104448
#define SMO_W0 (SMO_SS + 2048)        // 106496
#define SMEM_TOTAL 107008

// plain fp16 M^T: g_M[s][e][d] = SCALE * (Wq Wk^T)[d][e]
__device__ __align__(16) __half g_M[LOGN * DIM * DIM];

// ============================ helpers ============================
__device__ __forceinline__ uint32_t smem_u32(const void* p) {
    uint32_t a;
    asm("{ .reg .u64 t; cvta.to.shared.u64 t, %1; cvt.u32.u64 %0, t; }" : "=r"(a) : "l"(p));
    return a;
}
__device__ __forceinline__ void cpasync16(uint32_t dst, const void* src) {
    asm volatile("cp.async.cg.shared.global [%0], [%1], 16;" :: "r"(dst), "l"(src));
}
#define CPASYNC_COMMIT asm volatile("cp.async.commit_group;" ::: "memory")
#define CPASYNC_WAIT0  asm volatile("cp.async.wait_group 0;" ::: "memory")

#define LDSM4(r0, r1, r2, r3, addr) \
    asm volatile("ldmatrix.sync.aligned.m8n8.x4.shared.b16 {%0,%1,%2,%3}, [%4];" \
                 : "=r"(r0), "=r"(r1), "=r"(r2), "=r"(r3) : "r"(addr))

__device__ __forceinline__ void mma_f16(float* cd,
                                        uint32_t a0, uint32_t a1, uint32_t a2, uint32_t a3,
                                        uint32_t b0, uint32_t b1) {
    asm volatile("mma.sync.aligned.m16n8k16.row.col.f32.f16.f16.f32 "
                 "{%0,%1,%2,%3}, {%4,%5,%6,%7}, {%8,%9}, {%0,%1,%2,%3};"
                 : "+f"(cd[0]), "+f"(cd[1]), "+f"(cd[2]), "+f"(cd[3])
                 : "r"(a0), "r"(a1), "r"(a2), "r"(a3), "r"(b0), "r"(b1));
}
// insert a 0 bit at position ls (a-row index -> actual row)
__device__ __forceinline__ int insert0(int i, int ls) {
    return ((i >> ls) << (ls + 1)) | (i & ((1 << ls) - 1));
}

// ============================ precompute M^T (fp16) ============================
// g_M[s][e][d] = SCALE * sum_t Wq[d][t] * Wk[e][t]
__global__ void precompute_M_kernel(const float* __restrict__ w) {
    extern __shared__ float sm[];
    float* wqT  = sm;                 // [128][129] Wq transposed (padded)
    float* wk16 = sm + DIM * 129;     // 16 rows of Wk

    const int s    = blockIdx.x;
    const int eblk = blockIdx.y * 16;
    const float* Wq = w + (size_t)(2 * s) * DIM * DIM;
    const float* Wk = Wq + DIM * DIM;

    for (int i = threadIdx.x; i < DIM * DIM; i += 512) {
        int d = i >> 7, t = i & 127;
        wqT[t * 129 + d] = Wq[i];
    }
    for (int i = threadIdx.x; i < 16 * DIM; i += 512)
        wk16[i] = Wk[(size_t)eblk * DIM + i];
    __syncthreads();

    const int d  = threadIdx.x & 127;
    const int ee = threadIdx.x >> 7;          // 0..3
    #pragma unroll
    for (int k = 0; k < 4; k++) {
        int el = ee * 4 + k;
        float acc = 0.0f;
        #pragma unroll 8
        for (int t = 0; t < DIM; t++)
            acc += wk16[el * DIM + t] * wqT[t * 129 + d];
        g_M[((size_t)s * DIM + (eblk + el)) * DIM + d] = __float2half(acc * SCALE);
    }
}

// ============================ fused butterfly ============================
// mode 0: rows = blk*128 + rr                               (stages 0..6)
// mode 1: rows = batch*8192 + t0 + 64*(rr>>6) + 128*(rr&63) (stages 7..12)
__device__ __forceinline__ int grow_of(int mode, int blk, int rr) {
    if (mode == 0) return blk * 128 + rr;
    int batch = blk >> 6, t0 = blk & 63;
    return batch * 8192 + t0 + ((rr >> 6) << 6) + ((rr & 63) << 7);
}

__device__ __forceinline__ void prefetch_M(uint32_t sb, int buf, int stage, int tid) {
    const char* src = (const char*)(g_M + (size_t)stage * DIM * DIM);
    const uint32_t base = sb + SMO_M + (uint32_t)buf * MBUF;
    #pragma unroll
    for (int k = 0; k < 4; k++) {
        int i = tid + 512 * k;               // 2048 x 16B chunks
        int e = i >> 4, kc = i & 15;         // 16 chunks per 256B data row
        cpasync16(base + (uint32_t)(e * 272 + kc * 16), src + ((size_t)i << 4));
    }
    CPASYNC_COMMIT;
}

__global__ __launch_bounds__(THREADS, 1)
void butterfly_kernel(const float* __restrict__ x, float* __restrict__ out,
                      int nstages, int stage_off, int mode) {
    extern __shared__ char smem[];
    const uint32_t sb = smem_u32(smem);
    const __half2* Xh2 = (const __half2*)(smem + SMO_XH);
    float4* scr4  = (float4*)(smem + SMO_M);       // v staging (M region)
    float*  ssA   = (float*)(smem + SMO_SS);       // [4][64]
    float*  scA   = ssA + 256;                     // [4][64]
    float*  w0row = (float*)(smem + SMO_W0);       // [128]

    const int tid  = threadIdx.x;
    const int lane = tid & 31;
    const int wq   = tid >> 5;        // 16 warps
    const int blk  = blockIdx.x;
    const int mg   = wq >> 2;         // 0..3 : 16 a-rows (one m16 tile)
    const int nq   = wq & 3;          // 0..3 : 32 e-cols
    const int g    = lane >> 2;
    const int c    = lane & 3;

    // ---- x tile -> fp16 smem (coalesced); v rows staged fp32 into scratch ----
    for (int rr = wq; rr < 128; rr += 16) {
        int gr = grow_of(mode, blk, rr);
        float4 val = ((const float4*)x)[(size_t)gr * 32 + lane];
        __half2* dst = (__half2*)(smem + SMO_XH) + rr * 68 + lane * 2;
        dst[0] = __floats2half2_rn(val.x, val.y);
        dst[1] = __floats2half2_rn(val.z, val.w);
        if (mode == 0) scr4[rr * 33 + lane] = val;     // stage-0 v = x
    }
    if (mode != 0) {
        for (int rr = wq; rr < 128; rr += 16) {
            int gr = grow_of(1, blk, rr);
            scr4[rr * 33 + lane] = ((const float4*)out)[(size_t)gr * 32 + lane];
        }
    }
    __syncthreads();

    // ---- gather v: thread owns rows lane+32j (j=0..3), float4 cols wq*2+k ----
    float4 v[4][2];
    #pragma unroll
    for (int j = 0; j < 4; j++)
        #pragma unroll
        for (int k = 0; k < 2; k++)
            v[j][k] = scr4[(lane + 32 * j) * 33 + wq * 2 + k];
    __syncthreads();                     // scratch free -> M region usable

    prefetch_M(sb, 0, stage_off, tid);
    CPASYNC_WAIT0;
    __syncthreads();

    // ldmatrix lane roles
    const int lr   = lane & 7;
    const int rsel = (lane >> 3) & 1;    // A: row-group select
    const int akof = (lane >> 4) * 16;   // A: k-offset bytes
    const int esel = lane >> 4;          // B: e-group select
    const int bkof = ((lane >> 3) & 1) * 16;

    for (int ls = 0; ls < nstages; ls++) {
        const int cur = ls & 1;
        if (ls + 1 < nstages) prefetch_M(sb, cur ^ 1, stage_off + ls + 1, tid);

        // ---- MMA: Y[16 a-rows][32 e] = X_a * M^T ----
        const int ia_row = insert0(mg * 16 + rsel * 8 + lr, ls);
        const uint32_t abase = sb + SMO_XH + (uint32_t)(ia_row * 272) + akof;
        const uint32_t mb = sb + SMO_M + (uint32_t)cur * MBUF;
        const uint32_t bbase0 = mb + (uint32_t)((nq * 32 + esel * 8 + lr) * 272) + bkof;
        const uint32_t bbase1 = bbase0 + 16 * 272;

        float acc[4][4];
        #pragma unroll
        for (int nt = 0; nt < 4; nt++)
            #pragma unroll
            for (int q = 0; q < 4; q++) acc[nt][q] = 0.0f;

        #pragma unroll
        for (int kk = 0; kk < 8; kk++) {
            uint32_t a0, a1, a2, a3, b0, b1, b2, b3;
            LDSM4(a0, a1, a2, a3, abase + kk * 32);
            LDSM4(b0, b1, b2, b3, bbase0 + kk * 32);
            mma_f16(acc[0], a0, a1, a2, a3, b0, b1);
            mma_f16(acc[1], a0, a1, a2, a3, b2, b3);
            LDSM4(b0, b1, b2, b3, bbase1 + kk * 32);
            mma_f16(acc[2], a0, a1, a2, a3, b0, b1);
            mma_f16(acc[3], a0, a1, a2, a3, b2, b3);
        }

        // ---- dots: ss = y.xa, sc = y.xb ----
        {
            const int i0 = mg * 16 + g, i1 = i0 + 8;
            const int r0 = insert0(i0, ls), r1 = insert0(i1, ls);
            const int p0 = r0 | (1 << ls), p1 = r1 | (1 << ls);
            float ss0 = 0.f, sc0 = 0.f, ss1 = 0.f, sc1 = 0.f;
            #pragma unroll
            for (int nt = 0; nt < 4; nt++) {
                const int e2 = nq * 16 + nt * 4 + c;      // half2 col index
                float2 A0 = __half22float2(Xh2[r0 * 68 + e2]);
                float2 B0 = __half22float2(Xh2[p0 * 68 + e2]);
                float2 A1 = __half22float2(Xh2[r1 * 68 + e2]);
                float2 B1 = __half22float2(Xh2[p1 * 68 + e2]);
                ss0 += acc[nt][0] * A0.x + acc[nt][1] * A0.y;
                sc0 += acc[nt][0] * B0.x + acc[nt][1] * B0.y;
                ss1 += acc[nt][2] * A1.x + acc[nt][3] * A1.y;
                sc1 += acc[nt][2] * B1.x + acc[nt][3] * B1.y;
            }
            #pragma unroll
            for (int off = 1; off <= 2; off <<= 1) {
                ss0 += __shfl_xor_sync(0xffffffffu, ss0, off);
                sc0 += __shfl_xor_sync(0xffffffffu, sc0, off);
                ss1 += __shfl_xor_sync(0xffffffffu, ss1, off);
                sc1 += __shfl_xor_sync(0xffffffffu, sc1, off);
            }
            if (c == 0) {
                ssA[nq * 64 + i0] = ss0;  scA[nq * 64 + i0] = sc0;
                ssA[nq * 64 + i1] = ss1;  scA[nq * 64 + i1] = sc1;
            }
        }
        __syncthreads();

        // ---- pair weights ----
        if (tid < 64) {
            const int i = tid;
            float s1 = ssA[i] + ssA[64 + i] + ssA[128 + i] + ssA[192 + i];
            float s2 = scA[i] + scA[64 + i] + scA[128 + i] + scA[192 + i];
            float w0v = 1.0f / (1.0f + __expf(s2 - s1));   // own-row weight
            int ra = insert0(i, ls);
            w0row[ra] = w0v;
            w0row[ra | (1 << ls)] = w0v;
        }
        if (ls + 1 < nstages) CPASYNC_WAIT0;     // next M buffer complete
        __syncthreads();                          // w0row + M visibility

        // ---- butterfly mix of v (registers; shfl or local j-swap) ----
        {
            const int srr = 1 << ls;
            float w0v[4], w1v[4];
            #pragma unroll
            for (int j = 0; j < 4; j++) {
                w0v[j] = w0row[lane + 32 * j];
                w1v[j] = 1.0f - w0v[j];
            }
            if (srr <= 16) {
                #pragma unroll
                for (int j = 0; j < 4; j++)
                    #pragma unroll
                    for (int k = 0; k < 2; k++) {
                        float4 val = v[j][k];
                        float4 pv;
                        pv.x = __shfl_xor_sync(0xffffffffu, val.x, srr);
                        pv.y = __shfl_xor_sync(0xffffffffu, val.y, srr);
                        pv.z = __shfl_xor_sync(0xffffffffu, val.z, srr);
                        pv.w = __shfl_xor_sync(0xffffffffu, val.w, srr);
                        v[j][k].x = w0v[j] * val.x + w1v[j] * pv.x;
                        v[j][k].y = w0v[j] * val.y + w1v[j] * pv.y;
                        v[j][k].z = w0v[j] * val.z + w1v[j] * pv.z;
                        v[j][k].w = w0v[j] * val.w + w1v[j] * pv.w;
                    }
            } else {
                const int dj = srr >> 5;     // 1 (stride 32) or 2 (stride 64)
                #pragma unroll
                for (int k = 0; k < 2; k++) {
                    const float4 ps[4] = {v[0][k], v[1][k], v[2][k], v[3][k]};
                    #pragma unroll
                    for (int j = 0; j < 4; j++) {
                        float4 a = ps[j], b = ps[j ^ dj];
                        v[j][k].x = w0v[j] * a.x + w1v[j] * b.x;
                        v[j][k].y = w0v[j] * a.y + w1v[j] * b.y;
                        v[j][k].z = w0v[j] * a.z + w1v[j] * b.z;
                        v[j][k].w = w0v[j] * a.w + w1v[j] * b.w;
                    }
                }
            }
        }
    }

    // ---- v -> scratch -> coalesced global write (M region is dead now) ----
    #pragma unroll
    for (int j = 0; j < 4; j++)
        #pragma unroll
        for (int k = 0; k < 2; k++)
            scr4[(lane + 32 * j) * 33 + wq * 2 + k] = v[j][k];
    __syncthreads();
    for (int rr = wq; rr < 128; rr += 16) {
        int gr = grow_of(mode, blk, rr);
        ((float4*)out)[(size_t)gr * 32 + lane] = scr4[rr * 33 + lane];
    }
}

// ============================ launch ============================
extern "C" void kernel_launch(void* const* d_in, const int* in_sizes, int n_in,
                              void* d_out, int out_size) {
    const float* x = (const float*)d_in[0];   // (16, 8192, 128) f32
    const float* w = (const float*)d_in[1];   // (16, 2, 128, 128) f32
    float* out = (float*)d_out;

    const int smem_pre = (DIM * 129 + 16 * DIM) * 4;
    cudaFuncSetAttribute(precompute_M_kernel,
                         cudaFuncAttributeMaxDynamicSharedMemorySize, smem_pre);
    cudaFuncSetAttribute(butterfly_kernel,
                         cudaFuncAttributeMaxDynamicSharedMemorySize, SMEM_TOTAL);

    precompute_M_kernel<<<dim3(LOGN, 8), 512, smem_pre>>>(w);
    // stages 0..6 (strides 1..64): 128 contiguous rows per block
    butterfly_kernel<<<1024, THREADS, SMEM_TOTAL>>>(x, out, 7, 0, 0);
    // stages 7..12 (strides 128..4096): rows t0 + 64h + 128j per block
    butterfly_kernel<<<1024, THREADS, SMEM_TOTAL>>>(x, out, 6, 7, 1);
}

// round 8
// speedup vs baseline: 1.0644x; 1.0644x over previous
#include <cuda_runtime.h>
#include <cuda_fp16.h>
#include <cstdint>

#define DIM 128
#define LOGN 13
#define THREADS 256
#define SCALE 0.17677669529663688f   // 32^-0.5

// ---- dynamic smem byte offsets ----
// Xh : 128 rows x 66 half2 (fp16 x tile)
// M  : 2 buffers x 32 kc-rows x 136 uint2 (packed fp16 B-fragments)
// SS : 7 stages x 256 half2  (packed (ss, sc) partials per row-quarter)
// W0 : 7 stages x 64 f32 pair weights
#define SMO_XH 0
#define SMO_M  33792
#define MBUF   34816
#define SMO_SS (SMO_M + 2 * MBUF)     // 103424
#define SMO_W0 (SMO_SS + 7 * 1024)    // 110592
#define SMEM_TOTAL 112384

// packed fp16 M: [s][kc=kk*4+c][e][4 halves: k=2c,2c+1,2c+8,2c+9 of block kk]
__device__ __align__(16) __half g_Mh[LOGN * 32 * DIM * 4];

// ============================ helpers ============================
__device__ __forceinline__ uint32_t smem_u32(const void* p) {
    uint32_t a;
    asm("{ .reg .u64 t; cvta.to.shared.u64 t, %1; cvt.u32.u64 %0, t; }" : "=r"(a) : "l"(p));
    return a;
}
__device__ __forceinline__ void cpasync16(uint32_t dst, const void* src) {
    asm volatile("cp.async.cg.shared.global [%0], [%1], 16;" :: "r"(dst), "l"(src));
}
#define CPASYNC_COMMIT asm volatile("cp.async.commit_group;" ::: "memory")
#define CPASYNC_WAIT0  asm volatile("cp.async.wait_group 0;" ::: "memory")

__device__ __forceinline__ void mma_f16(float* cd,
                                        uint32_t a0, uint32_t a1, uint32_t a2, uint32_t a3,
                                        uint32_t b0, uint32_t b1) {
    asm volatile("mma.sync.aligned.m16n8k16.row.col.f32.f16.f16.f32 "
                 "{%0,%1,%2,%3}, {%4,%5,%6,%7}, {%8,%9}, {%0,%1,%2,%3};"
                 : "+f"(cd[0]), "+f"(cd[1]), "+f"(cd[2]), "+f"(cd[3])
                 : "r"(a0), "r"(a1), "r"(a2), "r"(a3), "r"(b0), "r"(b1));
}
// insert a 0 bit at position ls (a-row index -> actual row)
__device__ __forceinline__ int insert0(int i, int ls) {
    return ((i >> ls) << (ls + 1)) | (i & ((1 << ls) - 1));
}

// ============================ precompute M (fp16 B-frag layout) ============================
// M[d][e] = SCALE * sum_t Wq[d][t] * Wk[e][t]
__global__ void precompute_M_kernel(const float* __restrict__ w) {
    extern __shared__ float sm[];
    float* wkT  = sm;                 // [128][129] Wk transposed (padded)
    float* wq16 = sm + DIM * 129;     // 16 rows of Wq

    const int s    = blockIdx.x;
    const int dblk = blockIdx.y * 16;
    const float* Wq = w + (size_t)(2 * s) * DIM * DIM;
    const float* Wk = Wq + DIM * DIM;

    for (int i = threadIdx.x; i < DIM * DIM; i += 512) {
        int e = i >> 7, t = i & 127;
        wkT[t * 129 + e] = Wk[i];
    }
    for (int i = threadIdx.x; i < 16 * DIM; i += 512)
        wq16[i] = Wq[(size_t)dblk * DIM + i];
    __syncthreads();

    const int e  = threadIdx.x & 127;
    const int dd = threadIdx.x >> 7;          // 0..3, each handles 4 rows
    #pragma unroll
    for (int k = 0; k < 4; k++) {
        int rl = dd * 4 + k;
        float acc = 0.0f;
        #pragma unroll 8
        for (int t = 0; t < DIM; t++)
            acc += wq16[rl * DIM + t] * wkT[t * 129 + e];
        int d   = dblk + rl;
        int w16 = d & 15, kk = d >> 4;
        int c   = (w16 >> 1) & 3, hi = w16 >> 3, lo = w16 & 1;
        g_Mh[(((size_t)s * 32 + kk * 4 + c) * DIM + e) * 4 + hi * 2 + lo] =
            __float2half(acc * SCALE);
    }
}

// ============================ fused butterfly ============================
// mode 0: rows = blk*128 + rr                               (stages 0..6)
// mode 1: rows = batch*8192 + t0 + 64*(rr>>6) + 128*(rr&63) (stages 7..12)
__device__ __forceinline__ int grow_of(int mode, int blk, int rr) {
    if (mode == 0) return blk * 128 + rr;
    int batch = blk >> 6, t0 = blk & 63;
    return batch * 8192 + t0 + ((rr >> 6) << 6) + ((rr & 63) << 7);
}

__device__ __forceinline__ void prefetch_M(uint32_t sb, int buf, int stage, int tid) {
    const char* src = (const char*)(g_Mh + (size_t)stage * 32 * DIM * 4);
    const uint32_t base = sb + SMO_M + (uint32_t)buf * MBUF;
    #pragma unroll
    for (int k = 0; k < 8; k++) {
        int i  = tid + 256 * k;              // 2048 x 16B chunks
        int kc = i >> 6, e4 = i & 63;        // 64 chunks per kc row
        cpasync16(base + (uint32_t)(kc * 1088 + e4 * 16), src + ((size_t)i << 4));
    }
    CPASYNC_COMMIT;
}

__global__ __launch_bounds__(THREADS, 2)
void butterfly_kernel(const float* __restrict__ x, float* __restrict__ out,
                      int nstages, int stage_off, int mode) {
    extern __shared__ char smem[];
    const uint32_t sb = smem_u32(smem);
    const uint32_t* Xh32 = (const uint32_t*)(smem + SMO_XH);
    const __half2*  Xh2  = (const __half2*)(smem + SMO_XH);
    __half2* SSp  = (__half2*)(smem + SMO_SS);     // [7][256]
    float*  w0all = (float*)(smem + SMO_W0);       // [7][64]

    const int tid  = threadIdx.x;
    const int lane = tid & 31;
    const int wid  = tid >> 5;
    const int blk  = blockIdx.x;
    const int mg   = wid >> 2;        // 0..1 : 32 a-rows
    const int nq   = wid & 3;         // 0..3 : 32 e-cols
    const int g    = lane >> 2;
    const int c    = lane & 3;

    // ---- x tile -> fp16 smem (coalesced) ----
    for (int rr = wid; rr < 128; rr += 8) {
        int gr = grow_of(mode, blk, rr);
        float4 val = ((const float4*)x)[(size_t)gr * 32 + lane];
        __half2* dst = (__half2*)(smem + SMO_XH) + rr * 66 + lane * 2;
        dst[0] = __floats2half2_rn(val.x, val.y);
        dst[1] = __floats2half2_rn(val.z, val.w);
    }
    prefetch_M(sb, 0, stage_off, tid);

    // ---- v in registers straight from global ----
    float4 v[4][4];
    {
        const float4* vsrc = (mode == 0) ? (const float4*)x : (const float4*)out;
        #pragma unroll
        for (int j = 0; j < 4; j++) {
            int gr = grow_of(mode, blk, lane + 32 * j);
            #pragma unroll
            for (int k = 0; k < 4; k++)
                v[j][k] = vsrc[(size_t)gr * 32 + wid * 4 + k];
        }
    }
    CPASYNC_WAIT0;
    __syncthreads();

    // ================= Phase A: all stages' MMA + dots =================
    for (int ls = 0; ls < nstages; ls++) {
        const int cur = ls & 1;
        if (ls + 1 < nstages) prefetch_M(sb, cur ^ 1, stage_off + ls + 1, tid);

        // a-rows of this thread
        const int i0 = mg * 32 + g, i1 = i0 + 8, i2 = i0 + 16, i3 = i0 + 24;
        const int r0 = insert0(i0, ls), r1 = insert0(i1, ls);
        const int r2 = insert0(i2, ls), r3 = insert0(i3, ls);
        const int xb0 = r0 * 66, xb1 = r1 * 66, xb2 = r2 * 66, xb3 = r3 * 66;

        // ---- MMA: Y = X_a * M  (8 k16 steps, fp16 in / fp32 acc) ----
        float acc[2][4][4];
        #pragma unroll
        for (int t = 0; t < 2; t++)
            #pragma unroll
            for (int nt = 0; nt < 4; nt++)
                #pragma unroll
                for (int q = 0; q < 4; q++) acc[t][nt][q] = 0.0f;

        const uint2* Mb = (const uint2*)(smem + SMO_M + (uint32_t)cur * MBUF);
        #pragma unroll
        for (int kk = 0; kk < 8; kk++) {
            const int ia = kk * 8 + c;
            uint32_t a00 = Xh32[xb0 + ia], a01 = Xh32[xb1 + ia];
            uint32_t a02 = Xh32[xb0 + ia + 4], a03 = Xh32[xb1 + ia + 4];
            uint32_t a10 = Xh32[xb2 + ia], a11 = Xh32[xb3 + ia];
            uint32_t a12 = Xh32[xb2 + ia + 4], a13 = Xh32[xb3 + ia + 4];
            const uint2* bp = Mb + (kk * 4 + c) * 136 + nq * 32 + g;
            #pragma unroll
            for (int nt = 0; nt < 4; nt++) {
                uint2 b = bp[nt * 8];
                mma_f16(acc[0][nt], a00, a01, a02, a03, b.x, b.y);
                mma_f16(acc[1][nt], a10, a11, a12, a13, b.x, b.y);
            }
        }

        // ---- dots: ss = y.xa, sc = y.xb  (fp16 x reads) ----
        {
            const int p0 = r0 | (1 << ls), p1 = r1 | (1 << ls);
            const int p2 = r2 | (1 << ls), p3 = r3 | (1 << ls);
            float ss0 = 0.f, ss1 = 0.f, ss2 = 0.f, ss3 = 0.f;
            float sc0 = 0.f, sc1 = 0.f, sc2 = 0.f, sc3 = 0.f;
            #pragma unroll
            for (int nt = 0; nt < 4; nt++) {
                const int e2 = nq * 16 + nt * 4 + c;      // half2 col index
                float2 A0 = __half22float2(Xh2[r0 * 66 + e2]);
                float2 B0 = __half22float2(Xh2[p0 * 66 + e2]);
                float2 A1 = __half22float2(Xh2[r1 * 66 + e2]);
                float2 B1 = __half22float2(Xh2[p1 * 66 + e2]);
                float2 A2 = __half22float2(Xh2[r2 * 66 + e2]);
                float2 B2 = __half22float2(Xh2[p2 * 66 + e2]);
                float2 A3 = __half22float2(Xh2[r3 * 66 + e2]);
                float2 B3 = __half22float2(Xh2[p3 * 66 + e2]);
                ss0 += acc[0][nt][0] * A0.x + acc[0][nt][1] * A0.y;
                sc0 += acc[0][nt][0] * B0.x + acc[0][nt][1] * B0.y;
                ss1 += acc[0][nt][2] * A1.x + acc[0][nt][3] * A1.y;
                sc1 += acc[0][nt][2] * B1.x + acc[0][nt][3] * B1.y;
                ss2 += acc[1][nt][0] * A2.x + acc[1][nt][1] * A2.y;
                sc2 += acc[1][nt][0] * B2.x + acc[1][nt][1] * B2.y;
                ss3 += acc[1][nt][2] * A3.x + acc[1][nt][3] * A3.y;
                sc3 += acc[1][nt][2] * B3.x + acc[1][nt][3] * B3.y;
            }
            #pragma unroll
            for (int off = 1; off <= 2; off <<= 1) {
                ss0 += __shfl_xor_sync(0xffffffffu, ss0, off);
                sc0 += __shfl_xor_sync(0xffffffffu, sc0, off);
                ss1 += __shfl_xor_sync(0xffffffffu, ss1, off);
                sc1 += __shfl_xor_sync(0xffffffffu, sc1, off);
                ss2 += __shfl_xor_sync(0xffffffffu, ss2, off);
                sc2 += __shfl_xor_sync(0xffffffffu, sc2, off);
                ss3 += __shfl_xor_sync(0xffffffffu, ss3, off);
                sc3 += __shfl_xor_sync(0xffffffffu, sc3, off);
            }
            if (c == 0) {
                __half2* S = SSp + ls * 256 + nq * 64;
                S[i0] = __floats2half2_rn(ss0, sc0);
                S[i1] = __floats2half2_rn(ss1, sc1);
                S[i2] = __floats2half2_rn(ss2, sc2);
                S[i3] = __floats2half2_rn(ss3, sc3);
            }
        }
        if (ls + 1 < nstages) CPASYNC_WAIT0;   // next M buffer landed
        __syncthreads();                        // M handoff (+ final SS flush)
    }

    // ================= Phase B: all pair weights in one pass =================
    #pragma unroll
    for (int r = 0; r < 2; r++) {
        int j = tid + 256 * r;
        if (j < 64 * nstages) {
            int s = j >> 6, i = j & 63;
            const __half2* S = SSp + s * 256;
            float2 p0 = __half22float2(S[i]);
            float2 p1 = __half22float2(S[64 + i]);
            float2 p2 = __half22float2(S[128 + i]);
            float2 p3 = __half22float2(S[192 + i]);
            float s1 = p0.x + p1.x + p2.x + p3.x;
            float s2 = p0.y + p1.y + p2.y + p3.y;
            w0all[s * 64 + i] = 1.0f / (1.0f + __expf(s2 - s1));
        }
    }
    __syncthreads();

    // ================= Phase C: chained v mixes, zero syncs =================
    for (int ls = 0; ls < nstages; ls++) {
        const int srr = 1 << ls;
        float w0v[4], w1v[4];
        #pragma unroll
        for (int j = 0; j < 4; j++) {
            int row = lane + 32 * j;
            int idx = ((row >> (ls + 1)) << ls) | (row & (srr - 1));
            w0v[j] = w0all[ls * 64 + idx];
            w1v[j] = 1.0f - w0v[j];
        }
        if (srr <= 16) {
            #pragma unroll
            for (int j = 0; j < 4; j++)
                #pragma unroll
                for (int k = 0; k < 4; k++) {
                    float4 val = v[j][k];
                    float4 pv;
                    pv.x = __shfl_xor_sync(0xffffffffu, val.x, srr);
                    pv.y = __shfl_xor_sync(0xffffffffu, val.y, srr);
                    pv.z = __shfl_xor_sync(0xffffffffu, val.z, srr);
                    pv.w = __shfl_xor_sync(0xffffffffu, val.w, srr);
                    v[j][k].x = w0v[j] * val.x + w1v[j] * pv.x;
                    v[j][k].y = w0v[j] * val.y + w1v[j] * pv.y;
                    v[j][k].z = w0v[j] * val.z + w1v[j] * pv.z;
                    v[j][k].w = w0v[j] * val.w + w1v[j] * pv.w;
                }
        } else {
            const int dj = srr >> 5;     // 1 (stride 32) or 2 (stride 64)
            #pragma unroll
            for (int k = 0; k < 4; k++) {
                const float4 ps[4] = {v[0][k], v[1][k], v[2][k], v[3][k]};
                #pragma unroll
                for (int j = 0; j < 4; j++) {
                    float4 a = ps[j], b = ps[j ^ dj];
                    v[j][k].x = w0v[j] * a.x + w1v[j] * b.x;
                    v[j][k].y = w0v[j] * a.y + w1v[j] * b.y;
                    v[j][k].z = w0v[j] * a.z + w1v[j] * b.z;
                    v[j][k].w = w0v[j] * a.w + w1v[j] * b.w;
                }
            }
        }
    }

    // ---- write v to out ----
    #pragma unroll
    for (int j = 0; j < 4; j++) {
        int gr = grow_of(mode, blk, lane + 32 * j);
        #pragma unroll
        for (int k = 0; k < 4; k++)
            ((float4*)out)[(size_t)gr * 32 + wid * 4 + k] = v[j][k];
    }
}

// ============================ launch ============================
extern "C" void kernel_launch(void* const* d_in, const int* in_sizes, int n_in,
                              void* d_out, int out_size) {
    const float* x = (const float*)d_in[0];   // (16, 8192, 128) f32
    const float* w = (const float*)d_in[1];   // (16, 2, 128, 128) f32
    float* out = (float*)d_out;

    const int smem_pre = (DIM * 129 + 16 * DIM) * 4;
    cudaFuncSetAttribute(precompute_M_kernel,
                         cudaFuncAttributeMaxDynamicSharedMemorySize, smem_pre);
    cudaFuncSetAttribute(butterfly_kernel,
                         cudaFuncAttributeMaxDynamicSharedMemorySize, SMEM_TOTAL);

    precompute_M_kernel<<<dim3(LOGN, 8), 512, smem_pre>>>(w);
    // stages 0..6 (strides 1..64): 128 contiguous rows per block
    butterfly_kernel<<<1024, THREADS, SMEM_TOTAL>>>(x, out, 7, 0, 0);
    // stages 7..12 (strides 128..4096): rows t0 + 64h + 128j per block
    butterfly_kernel<<<1024, THREADS, SMEM_TOTAL>>>(x, out, 6, 7, 1);
}